// round 8
// baseline (speedup 1.0000x reference)
#include <cuda_runtime.h>
#include <math.h>
#include <stdint.h>

// GAT layer, fixed shapes per reference
#define NDIM   128   // IN_DIM
#define D      64    // OUT_DIM
#define EIN    32
#define EOUT   32
#define MAXN   50000
#define MAXE   1600000
#define SCAN_BS 1024

// ---- scratch (static device allocations; no runtime alloc) ----
__device__ float  g_z   [MAXN * D];     // z (zero-indeg fallback)
__device__ float  g_T1  [MAXN * D];     // z @ W_tonode[:64]
__device__ float  g_A1  [MAXN];
__device__ float  g_A2  [MAXN];
__device__ float  g_P1  [MAXN * EOUT];
__device__ float  g_P2  [MAXN * EOUT];
__device__ int    g_deg [MAXN];
__device__ int    g_rs  [MAXN + 1];     // CSR row starts (by dst)
__device__ int    g_cur [MAXN];
__device__ int    g_bsum[64];
__device__ int    g_boff[64];
__device__ float4 g_meta[MAXE];         // (ex, src, edge, 0) per sorted slot

// ---- packed f32x2 FMA helpers (FFMA2) ----
__device__ __forceinline__ uint64_t pack2(float x, float y) {
    uint64_t r; asm("mov.b64 %0, {%1, %2};" : "=l"(r) : "f"(x), "f"(y)); return r;
}
__device__ __forceinline__ void unpack2(uint64_t v, float& x, float& y) {
    asm("mov.b64 {%0, %1}, %2;" : "=f"(x), "=f"(y) : "l"(v));
}
__device__ __forceinline__ void fma2(uint64_t& acc, uint64_t a, uint64_t b) {
    asm("fma.rn.f32x2 %0, %1, %2, %0;" : "+l"(acc) : "l"(a), "l"(b));
}

// ---------------------------------------------------------------------------
__global__ void k_init(int N) {
    int i = blockIdx.x * blockDim.x + threadIdx.x;
    if (i < N) g_deg[i] = 0;
}

__global__ void k_hist(const int* __restrict__ dst, int E) {
    int e = blockIdx.x * blockDim.x + threadIdx.x;
    if (e < E) atomicAdd(&g_deg[dst[e]], 1);
}

__global__ void k_scan1(int N) {
    __shared__ int s[SCAN_BS];
    int i = blockIdx.x * SCAN_BS + threadIdx.x;
    s[threadIdx.x] = (i < N) ? g_deg[i] : 0;
    __syncthreads();
    for (int off = SCAN_BS >> 1; off > 0; off >>= 1) {
        if (threadIdx.x < off) s[threadIdx.x] += s[threadIdx.x + off];
        __syncthreads();
    }
    if (threadIdx.x == 0) g_bsum[blockIdx.x] = s[0];
}

// ---------------------------------------------------------------------------
// K-EMBED v2 (4th launch -> profiled): register-tiled 4 nodes x 4 cols/thread.
// sHT[k][node] transposed staging (pad 65, conflict-free); sZT aliases sHT.
// z = h@Wn; T1 = z@Wt1; A1/A2 = z.Wa. ~2.5 B LDS per MAC (was ~5).
// ---------------------------------------------------------------------------
__global__ void k_embed(const float* __restrict__ h, const float* __restrict__ Wn,
                        const float* __restrict__ Wt, const float* __restrict__ Wa, int N) {
    __shared__ float sWn[NDIM * D];       // 32 KB  [k][c]
    __shared__ float sHT[NDIM * 65];      // 33.3 KB [k][node]; sZT aliases rows 0..63
    __shared__ float sWa[2 * D];
    float* sZT = sHT;                     // [k<64][65]

    for (int i = threadIdx.x; i < NDIM * D; i += 256) sWn[i] = Wn[i];
    if (threadIdx.x < 2 * D) sWa[threadIdx.x] = Wa[threadIdx.x];

    int colg  = threadIdx.x & 15;         // cols 4*colg..+3
    int nodeg = threadIdx.x >> 4;         // nodes 4*nodeg..+3
    int c0 = colg << 2;
    int n0 = nodeg << 2;

    int nTiles = (N + 63) >> 6;
    for (int tile = blockIdx.x; tile < nTiles; tile += gridDim.x) {
        int base = tile << 6;
        __syncthreads();                  // protect sHT/sZT reuse
        // stage h[base..base+63][:] transposed; coalesced loads, stride-65 stores
        for (int i = threadIdx.x; i < 64 * 32; i += 256) {
            int r  = i >> 5;              // node 0..63
            int c4 = (i & 31) << 2;       // col 0..124
            float4 v = make_float4(0.f, 0.f, 0.f, 0.f);
            if (base + r < N) v = *(const float4*)&h[(size_t)(base + r) * NDIM + c4];
            sHT[(c4    ) * 65 + r] = v.x;
            sHT[(c4 + 1) * 65 + r] = v.y;
            sHT[(c4 + 2) * 65 + r] = v.z;
            sHT[(c4 + 3) * 65 + r] = v.w;
        }
        __syncthreads();
        // ---- z = h @ Wn : acc[node][2 f32x2] ----
        uint64_t za[4][2];
        #pragma unroll
        for (int n = 0; n < 4; n++) { za[n][0] = pack2(0.f, 0.f); za[n][1] = za[n][0]; }
        #pragma unroll 4
        for (int k = 0; k < NDIM; k++) {
            const float* hr = &sHT[k * 65 + n0];
            float4 wv = *(const float4*)&sWn[k * D + c0];
            uint64_t w01 = pack2(wv.x, wv.y), w23 = pack2(wv.z, wv.w);
            #pragma unroll
            for (int n = 0; n < 4; n++) {
                float hn = hr[n];
                uint64_t hh = pack2(hn, hn);
                fma2(za[n][0], w01, hh);
                fma2(za[n][1], w23, hh);
            }
        }
        float zr[4][4];
        #pragma unroll
        for (int n = 0; n < 4; n++) {
            unpack2(za[n][0], zr[n][0], zr[n][1]);
            unpack2(za[n][1], zr[n][2], zr[n][3]);
        }
        // store g_z + A1/A2 partials
        #pragma unroll
        for (int n = 0; n < 4; n++) {
            int node = base + n0 + n;
            if (node < N)
                *(float4*)&g_z[(size_t)node * D + c0] = make_float4(zr[n][0], zr[n][1], zr[n][2], zr[n][3]);
        }
        float p1[4], p2[4];
        #pragma unroll
        for (int n = 0; n < 4; n++) {
            p1[n] = zr[n][0]*sWa[c0] + zr[n][1]*sWa[c0+1] + zr[n][2]*sWa[c0+2] + zr[n][3]*sWa[c0+3];
            p2[n] = zr[n][0]*sWa[D+c0] + zr[n][1]*sWa[D+c0+1] + zr[n][2]*sWa[D+c0+2] + zr[n][3]*sWa[D+c0+3];
        }
        #pragma unroll
        for (int off = 8; off >= 1; off >>= 1) {
            #pragma unroll
            for (int n = 0; n < 4; n++) {
                p1[n] += __shfl_down_sync(0xffffffffu, p1[n], off, 16);
                p2[n] += __shfl_down_sync(0xffffffffu, p2[n], off, 16);
            }
        }
        __syncthreads();                  // all sHT reads done -> safe to write sZT
        // write z transposed: sZT[c][node]
        #pragma unroll
        for (int j = 0; j < 4; j++) {
            float* zc = &sZT[(c0 + j) * 65 + n0];
            zc[0] = zr[0][j]; zc[1] = zr[1][j]; zc[2] = zr[2][j]; zc[3] = zr[3][j];
        }
        if (colg == 0) {
            #pragma unroll
            for (int n = 0; n < 4; n++) {
                int node = base + n0 + n;
                if (node < N) { g_A1[node] = p1[n]; g_A2[node] = p2[n]; }
            }
        }
        __syncthreads();
        // ---- T1 = z @ Wt1 (Wt rows 0..63 via L1) ----
        uint64_t ta[4][2];
        #pragma unroll
        for (int n = 0; n < 4; n++) { ta[n][0] = pack2(0.f, 0.f); ta[n][1] = ta[n][0]; }
        #pragma unroll 4
        for (int k = 0; k < D; k++) {
            const float* zc = &sZT[k * 65 + n0];
            float4 wv = __ldg((const float4*)&Wt[k * D + c0]);
            uint64_t w01 = pack2(wv.x, wv.y), w23 = pack2(wv.z, wv.w);
            #pragma unroll
            for (int n = 0; n < 4; n++) {
                float zn = zc[n];
                uint64_t zz = pack2(zn, zn);
                fma2(ta[n][0], w01, zz);
                fma2(ta[n][1], w23, zz);
            }
        }
        #pragma unroll
        for (int n = 0; n < 4; n++) {
            int node = base + n0 + n;
            if (node < N) {
                float4 o;
                unpack2(ta[n][0], o.x, o.y);
                unpack2(ta[n][1], o.z, o.w);
                *(float4*)&g_T1[(size_t)node * D + c0] = o;
            }
        }
    }
}

__global__ void k_scan2(int NB, int N, int E) {
    if (threadIdx.x == 0) {
        int acc = 0;
        for (int b = 0; b < NB; b++) { g_boff[b] = acc; acc += g_bsum[b]; }
        g_rs[N] = E;
    }
}

__global__ void k_scan3(int N) {
    __shared__ int s[SCAN_BS];
    int i = blockIdx.x * SCAN_BS + threadIdx.x;
    int v = (i < N) ? g_deg[i] : 0;
    s[threadIdx.x] = v;
    __syncthreads();
    for (int off = 1; off < SCAN_BS; off <<= 1) {
        int x = (threadIdx.x >= off) ? s[threadIdx.x - off] : 0;
        __syncthreads();
        s[threadIdx.x] += x;
        __syncthreads();
    }
    if (i < N) {
        int excl = g_boff[blockIdx.x] + s[threadIdx.x] - v;
        g_rs[i]  = excl;
        g_cur[i] = excl;
    }
}

// ---------------------------------------------------------------------------
// K-SCAT: fused logit+exp + packed metadata (one 16B store per edge)
// ---------------------------------------------------------------------------
__global__ void k_scat(const float* __restrict__ ew, const float* __restrict__ Wa,
                       const int* __restrict__ src, const int* __restrict__ dst, int E) {
    __shared__ float sWa3[EIN];
    if (threadIdx.x < EIN) sWa3[threadIdx.x] = Wa[2 * D + threadIdx.x];
    __syncthreads();
    int e = blockIdx.x * blockDim.x + threadIdx.x;
    if (e >= E) return;
    int s = src[e], d = dst[e];
    const float4* r = (const float4*)(ew + (size_t)e * EIN);
    float a = __ldg(&g_A1[s]) + __ldg(&g_A2[d]);
    #pragma unroll
    for (int j = 0; j < 8; j++) {
        float4 v = r[j];
        a += v.x * sWa3[4*j] + v.y * sWa3[4*j+1] + v.z * sWa3[4*j+2] + v.w * sWa3[4*j+3];
    }
    float lr = (a >= 0.f) ? a : 0.1f * a;
    float ex = __expf(lr);
    int pos = atomicAdd(&g_cur[d], 1);
    g_meta[pos] = make_float4(ex, __int_as_float(s), __int_as_float(e), 0.f);
}

// ---------------------------------------------------------------------------
// K-AGG: warp per dst-node. 4 LDG/edge (1 uniform packed meta + 3 gathers).
// Fused epilogue: h_new = S/den + (G/den)@Wt2 (or z), out_h, P1/P2.
// ---------------------------------------------------------------------------
__global__ void k_agg(const float* __restrict__ ew, const float* __restrict__ Wt2,
                      const float* __restrict__ We, float* __restrict__ out_h, int N) {
    __shared__ float sWt2[EIN * D];       // 8 KB
    __shared__ float sWe[2 * D * EOUT];   // 16 KB
    __shared__ float sStage[8][96];
    for (int i = threadIdx.x; i < EIN * D; i += 256) sWt2[i] = Wt2[i];
    for (int i = threadIdx.x; i < 2 * D * EOUT; i += 256) sWe[i] = We[i];
    __syncthreads();
    int lane = threadIdx.x & 31;
    int wl = threadIdx.x >> 5;
    int gw = blockIdx.x * 8 + wl;
    int nwarps = gridDim.x * 8;
    for (int n = gw; n < N; n += nwarps) {
        int beg = g_rs[n], end = g_rs[n + 1];
        float S0 = 0.f, S1 = 0.f, G = 0.f, den = 0.f;
        #pragma unroll 4
        for (int i = beg; i < end; i++) {
            float4 md = __ldg(&g_meta[i]);        // warp-uniform, L1 hit
            float ex = md.x;
            int   s  = __float_as_int(md.y);
            int   e  = __float_as_int(md.z);
            float t0 = __ldg(&g_T1[(size_t)s * D + lane]);
            float t1 = __ldg(&g_T1[(size_t)s * D + 32 + lane]);
            float w  = __ldg(&ew[(size_t)e * EIN + lane]);
            den += ex;
            S0 += ex * t0;
            S1 += ex * t1;
            G  += ex * w;
        }
        float h0, h1;
        if (beg < end) {
            float inv = 1.f / den;
            sStage[wl][lane] = G * inv;
            __syncwarp();
            float gw0 = 0.f, gw1 = 0.f;
            #pragma unroll 8
            for (int k = 0; k < EIN; k++) {
                float gk = sStage[wl][k];
                gw0 += gk * sWt2[k * D + lane];
                gw1 += gk * sWt2[k * D + lane + 32];
            }
            h0 = S0 * inv + gw0;
            h1 = S1 * inv + gw1;
        } else {
            h0 = g_z[(size_t)n * D + lane];
            h1 = g_z[(size_t)n * D + 32 + lane];
        }
        size_t off = (size_t)n * D;
        out_h[off + lane]      = h0;
        out_h[off + 32 + lane] = h1;
        sStage[wl][32 + lane] = h0;
        sStage[wl][64 + lane] = h1;
        __syncwarp();
        float p1 = 0.f, p2 = 0.f;
        #pragma unroll 8
        for (int k = 0; k < D; k++) {
            float hv = sStage[wl][32 + k];
            p1 += hv * sWe[k * EOUT + lane];
            p2 += hv * sWe[(D + k) * EOUT + lane];
        }
        g_P1[(size_t)n * EOUT + lane] = p1;
        g_P2[(size_t)n * EOUT + lane] = p2;
        __syncwarp();
    }
}

// ---------------------------------------------------------------------------
// K-WNEW v2: register-tiled 4 edges x 8 cols/thread.
// w_new = P1[src] + P2[dst] + ew @ We3
// ---------------------------------------------------------------------------
__global__ void k_wnew(const float* __restrict__ ew, const float* __restrict__ We3,
                       const int* __restrict__ src, const int* __restrict__ dst,
                       float* __restrict__ out_w, int E) {
    __shared__ float sW[EIN * EOUT];      // 4 KB
    __shared__ float sEw[256 * 33];       // 33.8 KB
    for (int i = threadIdx.x; i < EIN * EOUT; i += 256) sW[i] = We3[i];
    int colg = threadIdx.x & 3;
    int c8 = colg << 3;
    int eg = threadIdx.x >> 2;            // edges 4*eg..+3 within tile
    int nTiles = (E + 255) >> 8;
    for (int tile = blockIdx.x; tile < nTiles; tile += gridDim.x) {
        int base = tile << 8;
        __syncthreads();
        for (int i = threadIdx.x; i < 256 * EIN; i += 256) {
            int l = i >> 5, cc = i & 31;
            sEw[l * 33 + cc] = (base + l < E) ? ew[(size_t)base * EIN + i] : 0.f;
        }
        __syncthreads();
        int e0 = base + (eg << 2);
        if (e0 >= E) continue;
        bool full = (e0 + 4 <= E);
        uint64_t acc[4][4];
        int sv[4], dv[4];
        if (full) {
            int4 s4 = *(const int4*)&src[e0];
            int4 d4 = *(const int4*)&dst[e0];
            sv[0]=s4.x; sv[1]=s4.y; sv[2]=s4.z; sv[3]=s4.w;
            dv[0]=d4.x; dv[1]=d4.y; dv[2]=d4.z; dv[3]=d4.w;
        } else {
            #pragma unroll
            for (int j = 0; j < 4; j++) {
                sv[j] = (e0 + j < E) ? src[e0 + j] : 0;
                dv[j] = (e0 + j < E) ? dst[e0 + j] : 0;
            }
        }
        #pragma unroll
        for (int j = 0; j < 4; j++) {
            float4 a0 = *(const float4*)&g_P1[(size_t)sv[j] * EOUT + c8];
            float4 a1 = *(const float4*)&g_P1[(size_t)sv[j] * EOUT + c8 + 4];
            float4 b0 = *(const float4*)&g_P2[(size_t)dv[j] * EOUT + c8];
            float4 b1 = *(const float4*)&g_P2[(size_t)dv[j] * EOUT + c8 + 4];
            acc[j][0] = pack2(a0.x + b0.x, a0.y + b0.y);
            acc[j][1] = pack2(a0.z + b0.z, a0.w + b0.w);
            acc[j][2] = pack2(a1.x + b1.x, a1.y + b1.y);
            acc[j][3] = pack2(a1.z + b1.z, a1.w + b1.w);
        }
        int le = eg << 2;
        #pragma unroll 4
        for (int k = 0; k < EIN; k++) {
            const uint64_t* wp = reinterpret_cast<const uint64_t*>(&sW[k * EOUT + c8]);
            uint64_t w0 = wp[0], w1 = wp[1], w2 = wp[2], w3 = wp[3];
            #pragma unroll
            for (int j = 0; j < 4; j++) {
                float ek = sEw[(le + j) * 33 + k];
                uint64_t ekk = pack2(ek, ek);
                fma2(acc[j][0], w0, ekk);
                fma2(acc[j][1], w1, ekk);
                fma2(acc[j][2], w2, ekk);
                fma2(acc[j][3], w3, ekk);
            }
        }
        #pragma unroll
        for (int j = 0; j < 4; j++) {
            if (e0 + j < E) {
                float4 o0, o1;
                unpack2(acc[j][0], o0.x, o0.y);
                unpack2(acc[j][1], o0.z, o0.w);
                unpack2(acc[j][2], o1.x, o1.y);
                unpack2(acc[j][3], o1.z, o1.w);
                *(float4*)&out_w[(size_t)(e0 + j) * EOUT + c8]     = o0;
                *(float4*)&out_w[(size_t)(e0 + j) * EOUT + c8 + 4] = o1;
            }
        }
    }
}

// ---------------------------------------------------------------------------
extern "C" void kernel_launch(void* const* d_in, const int* in_sizes, int n_in,
                              void* d_out, int out_size) {
    const float* h   = (const float*)d_in[0];   // [N,128]
    const float* ew  = (const float*)d_in[1];   // [E,32]
    const float* Wn  = (const float*)d_in[2];   // [128,64]
    const float* Wa  = (const float*)d_in[3];   // [160,1]
    const float* Wt  = (const float*)d_in[4];   // [96,64]
    const float* We  = (const float*)d_in[5];   // [160,32]
    const int*   src = (const int*)d_in[6];     // [E]
    const int*   dst = (const int*)d_in[7];     // [E]

    int N = in_sizes[0] / NDIM;
    int E = in_sizes[6];

    float* out_h = (float*)d_out;               // [N,64]
    float* out_w = out_h + (size_t)N * D;       // [E,32]

    const int PERSIST = 1184;
    int NB = (N + SCAN_BS - 1) / SCAN_BS;
    int embedBlocks = (N + 63) / 64;
    if (embedBlocks > PERSIST) embedBlocks = PERSIST;

    k_init   <<<(N + 255) / 256, 256>>>(N);
    k_hist   <<<(E + 255) / 256, 256>>>(dst, E);
    k_scan1  <<<NB, SCAN_BS>>>(N);
    k_embed  <<<embedBlocks, 256>>>(h, Wn, Wt, Wa, N);   // 4th launch -> profiled
    k_scan2  <<<1, 32>>>(NB, N, E);
    k_scan3  <<<NB, SCAN_BS>>>(N);
    k_scat   <<<(E + 255) / 256, 256>>>(ew, Wa, src, dst, E);
    k_agg    <<<PERSIST, 256>>>(ew, Wt + D * D, We, out_h, N);
    k_wnew   <<<PERSIST, 256>>>(ew, We + 2 * D * EOUT, src, dst, out_w, E);
}